// round 2
// baseline (speedup 1.0000x reference)
#include <cuda_runtime.h>

#define NG   512      // number of graphs
#define DIM  480      // feature dim
#define V    120      // float4 groups per row
#define NCH  224      // total channels (128 scalar + 64 l1 + 32 l2)
#define NSC  128      // scalar channels
#define EPSV 1e-5f
#define NB   456      // blocks for streaming kernels (152 SMs * 3)
#define TPB  480      // 4 node-rows x 120 float4 lanes

// Per-graph statistics / parameters (scratch; re-zeroed every launch)
__device__ float g_sum  [NG * NSC];   // sum x   (scalar channels)
__device__ float g_sumsq[NG * NCH];   // sum x^2 per channel (over all d components)
__device__ float g_scale[NG * NCH];
__device__ float g_beta [NG * NCH];   // bias - mean*scale for scalars, 0 otherwise
__device__ int   g_is64;              // 1 if batch buffer is int64, 0 if int32

__device__ __forceinline__ int col_channel(int col) {
    if (col < 128) return col;                       // l=0
    if (col < 320) return 128 + (col - 128) / 3;     // l=1 (d=3)
    return 192 + (col - 320) / 5;                    // l=2 (d=5)
}

// Read batch id for node n under either dtype interpretation.
__device__ __forceinline__ int read_g(const void* __restrict__ b, int n, int is64) {
    if (is64) return (int)((const long long*)b)[n];
    return ((const int*)b)[n];
}

// Zero scratch + detect batch dtype.
// batch sorted in [0, NG); N even. 32-bit word [N-1] is an odd index:
// int64 buffer -> high half == 0 ; int32 buffer -> batch[N-1] > 0 (w.p. ~1).
__global__ void zero_kernel(const void* __restrict__ batch, int N) {
    int i = blockIdx.x * blockDim.x + threadIdx.x;
    if (i < NG * NSC) g_sum[i]   = 0.f;
    if (i < NG * NCH) g_sumsq[i] = 0.f;
    if (i == 0) {
        int w = ((const int*)batch)[N - 1];
        g_is64 = (w == 0) ? 1 : 0;
    }
}

// ---------------------------------------------------------------------------
// Pass 1: per-graph Σx (scalars) and Σx² (all channels).
// batch is sorted, so each thread keeps register accumulators and flushes
// with atomics only at segment boundaries (~2 per block).
// ---------------------------------------------------------------------------
__global__ __launch_bounds__(TPB, 3) void pass1_kernel(
    const float4* __restrict__ in4, const void* __restrict__ batch,
    int N, int chunk)
{
    const int is64 = g_is64;
    const int lane = threadIdx.x % V;
    const int row  = threadIdx.x / V;
    const int col0 = lane * 4;
    const int c0 = col_channel(col0),     c1 = col_channel(col0 + 1);
    const int c2 = col_channel(col0 + 2), c3 = col_channel(col0 + 3);
    const bool sc = (col0 < NSC);

    const int start = blockIdx.x * chunk;
    const int end   = min(start + chunk, N);

    float q0 = 0.f, q1 = 0.f, q2 = 0.f, q3 = 0.f;
    float s0 = 0.f, s1 = 0.f, s2 = 0.f, s3 = 0.f;
    int curg = -1;

    for (int n = start + row; n < end; n += 4) {
        int g = read_g(batch, n, is64);
        float4 x = in4[(size_t)n * V + lane];
        if (g != curg) {
            if (curg >= 0) {
                float* qs = g_sumsq + curg * NCH;
                atomicAdd(qs + c0, q0); atomicAdd(qs + c1, q1);
                atomicAdd(qs + c2, q2); atomicAdd(qs + c3, q3);
                if (sc) {
                    float* ss = g_sum + curg * NSC + col0;
                    atomicAdd(ss + 0, s0); atomicAdd(ss + 1, s1);
                    atomicAdd(ss + 2, s2); atomicAdd(ss + 3, s3);
                }
            }
            curg = g;
            q0 = q1 = q2 = q3 = 0.f;
            s0 = s1 = s2 = s3 = 0.f;
        }
        q0 = fmaf(x.x, x.x, q0); q1 = fmaf(x.y, x.y, q1);
        q2 = fmaf(x.z, x.z, q2); q3 = fmaf(x.w, x.w, q3);
        if (sc) { s0 += x.x; s1 += x.y; s2 += x.z; s3 += x.w; }
    }
    if (curg >= 0) {
        float* qs = g_sumsq + curg * NCH;
        atomicAdd(qs + c0, q0); atomicAdd(qs + c1, q1);
        atomicAdd(qs + c2, q2); atomicAdd(qs + c3, q3);
        if (sc) {
            float* ss = g_sum + curg * NSC + col0;
            atomicAdd(ss + 0, s0); atomicAdd(ss + 1, s1);
            atomicAdd(ss + 2, s2); atomicAdd(ss + 3, s3);
        }
    }
}

// ---------------------------------------------------------------------------
// Params: per (graph, channel) scale/beta. Counts via binary search on the
// sorted batch array (reference clamps counts to >= 1).
// ---------------------------------------------------------------------------
__device__ __forceinline__ int lower_bound_g(const void* __restrict__ b,
                                             int n, int key, int is64) {
    int lo = 0, hi = n;
    while (lo < hi) {
        int mid = (lo + hi) >> 1;
        if (read_g(b, mid, is64) < key) lo = mid + 1; else hi = mid;
    }
    return lo;
}

__global__ void params_kernel(const void* __restrict__ batch,
                              const float* __restrict__ w,
                              const float* __restrict__ bias, int N)
{
    const int g = blockIdx.x;
    const int t = threadIdx.x;
    const int is64 = g_is64;
    __shared__ int s_lo, s_hi;
    if (t == 0) s_lo = lower_bound_g(batch, N, g, is64);
    if (t == 1) s_hi = lower_bound_g(batch, N, g + 1, is64);
    __syncthreads();
    if (t >= NCH) return;

    float cnt = fmaxf((float)(s_hi - s_lo), 1.0f);
    float sq  = g_sumsq[g * NCH + t];
    float scale, beta;
    if (t < NSC) {
        float mean = g_sum[g * NSC + t] / cnt;
        float var  = fmaxf(sq / cnt - mean * mean, 0.0f);   // seg_mean((x-m)^2)
        scale = rsqrtf(var + EPSV) * w[t];
        beta  = bias[t] - mean * scale;
    } else {
        float d = (t < 192) ? 3.0f : 5.0f;
        float msq = fmaxf(sq / (d * cnt), 0.0f);
        scale = rsqrtf(msq + EPSV) * w[t];
        beta  = 0.f;
    }
    g_scale[g * NCH + t] = scale;
    g_beta [g * NCH + t] = beta;
}

// ---------------------------------------------------------------------------
// Pass 2: out = x * scale[channel] + beta[channel]. Per-thread scale/beta
// cached in registers, reloaded only when the node's graph changes.
// ---------------------------------------------------------------------------
__global__ __launch_bounds__(TPB, 3) void pass2_kernel(
    const float4* __restrict__ in4, const void* __restrict__ batch,
    float4* __restrict__ out4, int N, int chunk)
{
    const int is64 = g_is64;
    const int lane = threadIdx.x % V;
    const int row  = threadIdx.x / V;
    const int col0 = lane * 4;
    const int c0 = col_channel(col0),     c1 = col_channel(col0 + 1);
    const int c2 = col_channel(col0 + 2), c3 = col_channel(col0 + 3);

    const int start = blockIdx.x * chunk;
    const int end   = min(start + chunk, N);

    float4 scv = make_float4(0.f, 0.f, 0.f, 0.f);
    float4 btv = make_float4(0.f, 0.f, 0.f, 0.f);
    int curg = -1;

    for (int n = start + row; n < end; n += 4) {
        int g = read_g(batch, n, is64);
        float4 x = in4[(size_t)n * V + lane];
        if (g != curg) {
            curg = g;
            const float* sp = g_scale + g * NCH;
            const float* bp = g_beta  + g * NCH;
            scv = make_float4(sp[c0], sp[c1], sp[c2], sp[c3]);
            btv = make_float4(bp[c0], bp[c1], bp[c2], bp[c3]);
        }
        float4 o;
        o.x = fmaf(x.x, scv.x, btv.x);
        o.y = fmaf(x.y, scv.y, btv.y);
        o.z = fmaf(x.z, scv.z, btv.z);
        o.w = fmaf(x.w, scv.w, btv.w);
        out4[(size_t)n * V + lane] = o;
    }
}

// ---------------------------------------------------------------------------
extern "C" void kernel_launch(void* const* d_in, const int* in_sizes, int n_in,
                              void* d_out, int out_size)
{
    const float* inp   = (const float*)d_in[0];   // (N, 480) f32
    const float* w     = (const float*)d_in[1];   // (224,)   f32
    const float* bias  = (const float*)d_in[2];   // (128,)   f32
    const void*  batch = (const void*)d_in[3];    // (N,) int32 or int64, sorted
    float*       out   = (float*)d_out;

    const int N = in_sizes[0] / DIM;              // dtype-independent node count
    const int chunk = (N + NB - 1) / NB;

    zero_kernel<<<(NG * NCH + 1023) / 1024, 1024>>>(batch, N);
    pass1_kernel<<<NB, TPB>>>((const float4*)inp, batch, N, chunk);
    params_kernel<<<NG, 256>>>(batch, w, bias, N);
    pass2_kernel<<<NB, TPB>>>((const float4*)inp, batch, (float4*)out, N, chunk);
}

// round 5
// speedup vs baseline: 1.2136x; 1.2136x over previous
#include <cuda_runtime.h>

#define NG   512      // number of graphs
#define DIM  480      // feature dim
#define V    120      // float4 groups per row
#define NCH  224      // total channels (128 scalar + 64 l1 + 32 l2)
#define NSC  128      // scalar channels
#define EPSV 1e-5f
#define TPB  960      // 8 node-rows x 120 float4 lanes
#define ROWS 8

__device__ int g_off[NG + 1];   // g_off[g] = first node index with batch >= g

__device__ __forceinline__ int col_channel(int col) {
    if (col < 128) return col;                       // l=0
    if (col < 320) return 128 + (col - 128) / 3;     // l=1 (d=3)
    return 192 + (col - 320) / 5;                    // l=2 (d=5)
}

// Read batch id for node n under either dtype interpretation.
__device__ __forceinline__ int read_g(const void* __restrict__ b, int n, int is64) {
    if (is64) return (int)((const long long*)b)[n];
    return ((const int*)b)[n];
}

// batch sorted in [0, NG); N even. 32-bit word [N-1] is an odd index:
// int64 buffer -> high half == 0 ; int32 buffer -> batch[N-1] > 0 (w.p. ~1).
__device__ __forceinline__ int detect_is64(const void* __restrict__ b, int N) {
    return (((const int*)b)[N - 1] == 0) ? 1 : 0;
}

// ---------------------------------------------------------------------------
// Prep: boundary scan of sorted batch -> segment offsets g_off[0..NG].
// ---------------------------------------------------------------------------
__global__ void prep_kernel(const void* __restrict__ batch, int N) {
    const int is64 = detect_is64(batch, N);
    for (int n = blockIdx.x * blockDim.x + threadIdx.x; n < N;
         n += gridDim.x * blockDim.x) {
        int gn = read_g(batch, n, is64);
        if (n == 0) {
            for (int g = 0; g <= gn; g++) g_off[g] = 0;
        } else {
            int gp = read_g(batch, n - 1, is64);
            for (int g = gp + 1; g <= gn; g++) g_off[g] = n;
        }
        if (n == N - 1) {
            for (int g = gn + 1; g <= NG; g++) g_off[g] = N;
        }
    }
}

// ---------------------------------------------------------------------------
// Fused: one block per graph. Phase A: stats (first DRAM read, lines land in
// L2). Params in smem. Phase B: re-read (should hit L2, __ldcs evict-first) +
// streaming write (__stcs). Occupancy limited to 1 block/SM purely by
// register pressure (launch_bounds(960,1) + unroll-by-2 -> ~40 regs;
// 2 blocks would need <=34), so the concurrent reuse window
// (152 SM x ~750KB/graph ~ 114MB) fits in the 126MB L2.
// ---------------------------------------------------------------------------
__global__ __launch_bounds__(TPB, 1) void fused_kernel(
    const float4* __restrict__ in4, float4* __restrict__ out4,
    const float* __restrict__ w, const float* __restrict__ bias)
{
    __shared__ float s_sq[DIM];             // per-column sum of squares
    __shared__ float s_sum[NSC];            // per-column sum (scalar cols)
    __shared__ float s_scale[NCH], s_beta[NCH];
    __shared__ int s_lo, s_hi;

    const int g    = blockIdx.x;
    const int tid  = threadIdx.x;
    const int lane = tid % V;
    const int row  = tid / V;
    const int col0 = lane * 4;
    const int c0 = col_channel(col0),     c1 = col_channel(col0 + 1);
    const int c2 = col_channel(col0 + 2), c3 = col_channel(col0 + 3);
    const bool sc = (col0 < NSC);

    if (tid == 0) { s_lo = g_off[g]; s_hi = g_off[g + 1]; }
    for (int i = tid; i < DIM; i += TPB) s_sq[i] = 0.f;
    for (int i = tid; i < NSC; i += TPB) s_sum[i] = 0.f;
    __syncthreads();

    const int lo = s_lo, hi = s_hi;
    const float4* __restrict__ base = in4 + lane;

    // ---- Phase A: accumulate stats in registers (unrolled x2 for MLP and
    //      register pressure — the occupancy limiter) ----
    float q0 = 0.f, q1 = 0.f, q2 = 0.f, q3 = 0.f;
    float s0 = 0.f, s1 = 0.f, s2 = 0.f, s3 = 0.f;
    int n = lo + row;
    for (; n + ROWS < hi; n += 2 * ROWS) {
        float4 xa = __ldg(base + (size_t)n * V);
        float4 xb = __ldg(base + (size_t)(n + ROWS) * V);
        q0 = fmaf(xa.x, xa.x, q0); q1 = fmaf(xa.y, xa.y, q1);
        q2 = fmaf(xa.z, xa.z, q2); q3 = fmaf(xa.w, xa.w, q3);
        q0 = fmaf(xb.x, xb.x, q0); q1 = fmaf(xb.y, xb.y, q1);
        q2 = fmaf(xb.z, xb.z, q2); q3 = fmaf(xb.w, xb.w, q3);
        if (sc) {
            s0 += xa.x + xb.x; s1 += xa.y + xb.y;
            s2 += xa.z + xb.z; s3 += xa.w + xb.w;
        }
    }
    if (n < hi) {
        float4 x = __ldg(base + (size_t)n * V);
        q0 = fmaf(x.x, x.x, q0); q1 = fmaf(x.y, x.y, q1);
        q2 = fmaf(x.z, x.z, q2); q3 = fmaf(x.w, x.w, q3);
        if (sc) { s0 += x.x; s1 += x.y; s2 += x.z; s3 += x.w; }
    }
    atomicAdd(&s_sq[col0 + 0], q0); atomicAdd(&s_sq[col0 + 1], q1);
    atomicAdd(&s_sq[col0 + 2], q2); atomicAdd(&s_sq[col0 + 3], q3);
    if (sc) {
        atomicAdd(&s_sum[col0 + 0], s0); atomicAdd(&s_sum[col0 + 1], s1);
        atomicAdd(&s_sum[col0 + 2], s2); atomicAdd(&s_sum[col0 + 3], s3);
    }
    __syncthreads();

    // ---- Params: one thread per channel ----
    if (tid < NCH) {
        const int t = tid;
        float cnt = fmaxf((float)(hi - lo), 1.0f);
        float scale, beta;
        if (t < NSC) {
            float mean = s_sum[t] / cnt;
            float var  = fmaxf(s_sq[t] / cnt - mean * mean, 0.0f);
            scale = rsqrtf(var + EPSV) * w[t];
            beta  = bias[t] - mean * scale;
        } else if (t < 192) {
            int base_c = 128 + (t - 128) * 3;
            float sq = s_sq[base_c] + s_sq[base_c + 1] + s_sq[base_c + 2];
            scale = rsqrtf(sq / (3.0f * cnt) + EPSV) * w[t];
            beta  = 0.f;
        } else {
            int base_c = 320 + (t - 192) * 5;
            float sq = s_sq[base_c] + s_sq[base_c + 1] + s_sq[base_c + 2]
                     + s_sq[base_c + 3] + s_sq[base_c + 4];
            scale = rsqrtf(sq / (5.0f * cnt) + EPSV) * w[t];
            beta  = 0.f;
        }
        s_scale[t] = scale;
        s_beta[t]  = beta;
    }
    __syncthreads();

    // ---- Phase B: apply (reads should hit L2; stream both paths) ----
    const float4 scv = make_float4(s_scale[c0], s_scale[c1], s_scale[c2], s_scale[c3]);
    const float4 btv = make_float4(s_beta[c0],  s_beta[c1],  s_beta[c2],  s_beta[c3]);
    float4* __restrict__ obase = out4 + lane;
    n = lo + row;
    for (; n + ROWS < hi; n += 2 * ROWS) {
        float4 xa = __ldcs(base + (size_t)n * V);
        float4 xb = __ldcs(base + (size_t)(n + ROWS) * V);
        float4 oa, ob;
        oa.x = fmaf(xa.x, scv.x, btv.x); oa.y = fmaf(xa.y, scv.y, btv.y);
        oa.z = fmaf(xa.z, scv.z, btv.z); oa.w = fmaf(xa.w, scv.w, btv.w);
        ob.x = fmaf(xb.x, scv.x, btv.x); ob.y = fmaf(xb.y, scv.y, btv.y);
        ob.z = fmaf(xb.z, scv.z, btv.z); ob.w = fmaf(xb.w, scv.w, btv.w);
        __stcs(obase + (size_t)n * V, oa);
        __stcs(obase + (size_t)(n + ROWS) * V, ob);
    }
    if (n < hi) {
        float4 x = __ldcs(base + (size_t)n * V);
        float4 o;
        o.x = fmaf(x.x, scv.x, btv.x); o.y = fmaf(x.y, scv.y, btv.y);
        o.z = fmaf(x.z, scv.z, btv.z); o.w = fmaf(x.w, scv.w, btv.w);
        __stcs(obase + (size_t)n * V, o);
    }
}

// ---------------------------------------------------------------------------
extern "C" void kernel_launch(void* const* d_in, const int* in_sizes, int n_in,
                              void* d_out, int out_size)
{
    const float* inp   = (const float*)d_in[0];   // (N, 480) f32
    const float* w     = (const float*)d_in[1];   // (224,)   f32
    const float* bias  = (const float*)d_in[2];   // (128,)   f32
    const void*  batch = (const void*)d_in[3];    // (N,) int32 or int64, sorted
    float*       out   = (float*)d_out;

    const int N = in_sizes[0] / DIM;              // dtype-independent node count

    prep_kernel<<<304, 256>>>(batch, N);
    fused_kernel<<<NG, TPB>>>((const float4*)inp, (float4*)out, w, bias);
}

// round 6
// speedup vs baseline: 1.2784x; 1.0534x over previous
#include <cuda_runtime.h>
#include <cooperative_groups.h>

namespace cg = cooperative_groups;

#define NG   512      // number of graphs
#define DIM  480      // feature dim
#define V    120      // float4 groups per row
#define NCH  224      // total channels (128 scalar + 64 l1 + 32 l2)
#define NSC  128      // scalar channels
#define EPSV 1e-5f
#define TPB  960      // 8 node-rows x 120 float4 lanes
#define ROWS 8

__device__ int g_off[NG + 1];   // g_off[g] = first node index with batch >= g

__device__ __forceinline__ int col_channel(int col) {
    if (col < 128) return col;                       // l=0
    if (col < 320) return 128 + (col - 128) / 3;     // l=1 (d=3)
    return 192 + (col - 320) / 5;                    // l=2 (d=5)
}

// Read batch id for node n under either dtype interpretation.
__device__ __forceinline__ int read_g(const void* __restrict__ b, int n, int is64) {
    if (is64) return (int)((const long long*)b)[n];
    return ((const int*)b)[n];
}

// batch sorted in [0, NG); N even. 32-bit word [N-1] is an odd index:
// int64 buffer -> high half == 0 ; int32 buffer -> batch[N-1] > 0 (w.p. ~1).
__device__ __forceinline__ int detect_is64(const void* __restrict__ b, int N) {
    return (((const int*)b)[N - 1] == 0) ? 1 : 0;
}

// ---------------------------------------------------------------------------
// Prep: boundary scan of sorted batch -> segment offsets g_off[0..NG].
// ---------------------------------------------------------------------------
__global__ void prep_kernel(const void* __restrict__ batch, int N) {
    const int is64 = detect_is64(batch, N);
    for (int n = blockIdx.x * blockDim.x + threadIdx.x; n < N;
         n += gridDim.x * blockDim.x) {
        int gn = read_g(batch, n, is64);
        if (n == 0) {
            for (int g = 0; g <= gn; g++) g_off[g] = 0;
        } else {
            int gp = read_g(batch, n - 1, is64);
            for (int g = gp + 1; g <= gn; g++) g_off[g] = n;
        }
        if (n == N - 1) {
            for (int g = gn + 1; g <= NG; g++) g_off[g] = N;
        }
    }
}

// ---------------------------------------------------------------------------
// Fused, clustered: one GRAPH per 2-CTA cluster; each CTA handles half the
// graph's node slab (~375KB). Phase A: local stats in smem. cluster.sync,
// combine partial stats from the peer CTA via DSMEM, compute params.
// cluster.sync, then Phase B: re-read own half (L2-hot: concurrent window is
// 152 x 375KB ~ 57MB << 126MB L2) and write streaming.
// Occupancy kept at 1 block/SM by register pressure (launch_bounds(960,1),
// unroll x2 -> ~60 regs; 2 blocks would need <=34).
// ---------------------------------------------------------------------------
__global__ __launch_bounds__(TPB, 1) __cluster_dims__(2, 1, 1)
void fused_kernel(
    const float4* __restrict__ in4, float4* __restrict__ out4,
    const float* __restrict__ w, const float* __restrict__ bias)
{
    __shared__ float s_sq[DIM];             // per-column partial sum of squares
    __shared__ float s_sum[NSC];            // per-column partial sum (scalars)
    __shared__ float s_scale[NCH], s_beta[NCH];
    __shared__ int s_range[4];              // mylo, myhi, glo, ghi

    cg::cluster_group cluster = cg::this_cluster();
    const unsigned rank = cluster.block_rank();   // 0 or 1
    const int g    = blockIdx.x >> 1;
    const int tid  = threadIdx.x;
    const int lane = tid % V;
    const int row  = tid / V;
    const int col0 = lane * 4;
    const int c0 = col_channel(col0),     c1 = col_channel(col0 + 1);
    const int c2 = col_channel(col0 + 2), c3 = col_channel(col0 + 3);
    const bool sc = (col0 < NSC);

    if (tid == 0) {
        int glo = g_off[g], ghi = g_off[g + 1];
        int mid = (glo + ghi) >> 1;
        s_range[0] = rank ? mid : glo;
        s_range[1] = rank ? ghi : mid;
        s_range[2] = glo;
        s_range[3] = ghi;
    }
    for (int i = tid; i < DIM; i += TPB) s_sq[i] = 0.f;
    for (int i = tid; i < NSC; i += TPB) s_sum[i] = 0.f;
    __syncthreads();

    const int lo = s_range[0], hi = s_range[1];
    const float cntf = fmaxf((float)(s_range[3] - s_range[2]), 1.0f);
    const float4* __restrict__ base = in4 + lane;

    // ---- Phase A: accumulate partial stats over my half (unrolled x2) ----
    float q0 = 0.f, q1 = 0.f, q2 = 0.f, q3 = 0.f;
    float s0 = 0.f, s1 = 0.f, s2 = 0.f, s3 = 0.f;
    int n = lo + row;
    for (; n + ROWS < hi; n += 2 * ROWS) {
        float4 xa = __ldg(base + (size_t)n * V);
        float4 xb = __ldg(base + (size_t)(n + ROWS) * V);
        q0 = fmaf(xa.x, xa.x, q0); q1 = fmaf(xa.y, xa.y, q1);
        q2 = fmaf(xa.z, xa.z, q2); q3 = fmaf(xa.w, xa.w, q3);
        q0 = fmaf(xb.x, xb.x, q0); q1 = fmaf(xb.y, xb.y, q1);
        q2 = fmaf(xb.z, xb.z, q2); q3 = fmaf(xb.w, xb.w, q3);
        if (sc) {
            s0 += xa.x + xb.x; s1 += xa.y + xb.y;
            s2 += xa.z + xb.z; s3 += xa.w + xb.w;
        }
    }
    if (n < hi) {
        float4 x = __ldg(base + (size_t)n * V);
        q0 = fmaf(x.x, x.x, q0); q1 = fmaf(x.y, x.y, q1);
        q2 = fmaf(x.z, x.z, q2); q3 = fmaf(x.w, x.w, q3);
        if (sc) { s0 += x.x; s1 += x.y; s2 += x.z; s3 += x.w; }
    }
    atomicAdd(&s_sq[col0 + 0], q0); atomicAdd(&s_sq[col0 + 1], q1);
    atomicAdd(&s_sq[col0 + 2], q2); atomicAdd(&s_sq[col0 + 3], q3);
    if (sc) {
        atomicAdd(&s_sum[col0 + 0], s0); atomicAdd(&s_sum[col0 + 1], s1);
        atomicAdd(&s_sum[col0 + 2], s2); atomicAdd(&s_sum[col0 + 3], s3);
    }

    // ---- Combine partials across the CTA pair ----
    cluster.sync();   // partial stats of both CTAs visible cluster-wide

    const float* peer_sq  = cluster.map_shared_rank(s_sq,  rank ^ 1);
    const float* peer_sum = cluster.map_shared_rank(s_sum, rank ^ 1);

    if (tid < NCH) {
        const int t = tid;
        float scale, beta;
        if (t < NSC) {
            float mean = (s_sum[t] + peer_sum[t]) / cntf;
            float sq   = s_sq[t] + peer_sq[t];
            float var  = fmaxf(sq / cntf - mean * mean, 0.0f);
            scale = rsqrtf(var + EPSV) * w[t];
            beta  = bias[t] - mean * scale;
        } else if (t < 192) {
            int b0 = 128 + (t - 128) * 3;
            float sq = (s_sq[b0]     + peer_sq[b0])
                     + (s_sq[b0 + 1] + peer_sq[b0 + 1])
                     + (s_sq[b0 + 2] + peer_sq[b0 + 2]);
            scale = rsqrtf(sq / (3.0f * cntf) + EPSV) * w[t];
            beta  = 0.f;
        } else {
            int b0 = 320 + (t - 192) * 5;
            float sq = (s_sq[b0]     + peer_sq[b0])
                     + (s_sq[b0 + 1] + peer_sq[b0 + 1])
                     + (s_sq[b0 + 2] + peer_sq[b0 + 2])
                     + (s_sq[b0 + 3] + peer_sq[b0 + 3])
                     + (s_sq[b0 + 4] + peer_sq[b0 + 4]);
            scale = rsqrtf(sq / (5.0f * cntf) + EPSV) * w[t];
            beta  = 0.f;
        }
        s_scale[t] = scale;
        s_beta[t]  = beta;
    }

    // Barrier: params visible block-wide AND peer finished reading my s_sq.
    cluster.sync();

    // ---- Phase B: apply over my half (reads L2-hot; stream both paths) ----
    const float4 scv = make_float4(s_scale[c0], s_scale[c1], s_scale[c2], s_scale[c3]);
    const float4 btv = make_float4(s_beta[c0],  s_beta[c1],  s_beta[c2],  s_beta[c3]);
    float4* __restrict__ obase = out4 + lane;
    n = lo + row;
    for (; n + ROWS < hi; n += 2 * ROWS) {
        float4 xa = __ldcs(base + (size_t)n * V);
        float4 xb = __ldcs(base + (size_t)(n + ROWS) * V);
        float4 oa, ob;
        oa.x = fmaf(xa.x, scv.x, btv.x); oa.y = fmaf(xa.y, scv.y, btv.y);
        oa.z = fmaf(xa.z, scv.z, btv.z); oa.w = fmaf(xa.w, scv.w, btv.w);
        ob.x = fmaf(xb.x, scv.x, btv.x); ob.y = fmaf(xb.y, scv.y, btv.y);
        ob.z = fmaf(xb.z, scv.z, btv.z); ob.w = fmaf(xb.w, scv.w, btv.w);
        __stcs(obase + (size_t)n * V, oa);
        __stcs(obase + (size_t)(n + ROWS) * V, ob);
    }
    if (n < hi) {
        float4 x = __ldcs(base + (size_t)n * V);
        float4 o;
        o.x = fmaf(x.x, scv.x, btv.x); o.y = fmaf(x.y, scv.y, btv.y);
        o.z = fmaf(x.z, scv.z, btv.z); o.w = fmaf(x.w, scv.w, btv.w);
        __stcs(obase + (size_t)n * V, o);
    }
}

// ---------------------------------------------------------------------------
extern "C" void kernel_launch(void* const* d_in, const int* in_sizes, int n_in,
                              void* d_out, int out_size)
{
    const float* inp   = (const float*)d_in[0];   // (N, 480) f32
    const float* w     = (const float*)d_in[1];   // (224,)   f32
    const float* bias  = (const float*)d_in[2];   // (128,)   f32
    const void*  batch = (const void*)d_in[3];    // (N,) int32 or int64, sorted
    float*       out   = (float*)d_out;

    const int N = in_sizes[0] / DIM;              // dtype-independent node count

    prep_kernel<<<304, 256>>>(batch, N);
    fused_kernel<<<NG * 2, TPB>>>((const float4*)inp, (float4*)out, w, bias);
}